// round 1
// baseline (speedup 1.0000x reference)
#include <cuda_runtime.h>

namespace {
constexpr int B_ = 4, H_ = 160, W_ = 160, D_ = 160;
constexpr int SX = D_;            // stride of x (W axis)
constexpr int SY = W_ * D_;       // stride of y (H axis)
constexpr int SB = H_ * W_ * D_;  // stride of batch
constexpr int NVOX = B_ * SB;     // 16,384,000
constexpr int NQUAD = NVOX / 4;   // 4,096,000 (D=160 divisible by 4)

__device__ __forceinline__ float sample1(const float* __restrict__ im,
                                         int b, float xf, float yf, float zf) {
    // floor + clip exactly like the reference:
    //   x0 = clip(floor(x)); x1 = clip(floor(x)+1); ddx = float(x1) - x
    int x0 = (int)floorf(xf);
    int y0 = (int)floorf(yf);
    int z0 = (int)floorf(zf);
    int x1 = min(max(x0 + 1, 0), W_ - 1);
    int y1 = min(max(y0 + 1, 0), H_ - 1);
    int z1 = min(max(z0 + 1, 0), D_ - 1);
    x0 = min(max(x0, 0), W_ - 1);
    y0 = min(max(y0, 0), H_ - 1);
    z0 = min(max(z0, 0), D_ - 1);

    float ddx = (float)x1 - xf;
    float ddy = (float)y1 - yf;
    float ddz = (float)z1 - zf;
    float ex = 1.0f - ddx;
    float ey = 1.0f - ddy;
    float ez = 1.0f - ddz;

    const float* base = im + b * SB;
    const float* p00 = base + y0 * SY + x0 * SX;  // (y0, x0)
    const float* p10 = base + y1 * SY + x0 * SX;  // (y1, x0)
    const float* p01 = base + y0 * SY + x1 * SX;  // (y0, x1)
    const float* p11 = base + y1 * SY + x1 * SX;  // (y1, x1)

    float va = __ldg(p00 + z0);
    float vb = __ldg(p10 + z0);
    float vc = __ldg(p01 + z0);
    float vd = __ldg(p11 + z0);
    float ve = __ldg(p00 + z1);
    float vf = __ldg(p10 + z1);
    float vg = __ldg(p01 + z1);
    float vh = __ldg(p11 + z1);

    // wa = ddz*ddx*ddy etc. -> factor: z-plane0 = ddx*(ddy*va + ey*vb) + ex*(ddy*vc + ey*vd)
    float s0 = fmaf(ddx, fmaf(ddy, va, ey * vb), ex * fmaf(ddy, vc, ey * vd));
    float s1 = fmaf(ddx, fmaf(ddy, ve, ey * vf), ex * fmaf(ddy, vg, ey * vh));
    return fmaf(ddz, s0, ez * s1);
}
}  // namespace

__global__ void __launch_bounds__(256)
dense3d_warp_kernel(const float* __restrict__ im,
                    const float* __restrict__ flow,
                    float* __restrict__ out) {
    int t = blockIdx.x * blockDim.x + threadIdx.x;
    if (t >= NQUAD) return;

    int basevox = t * 4;  // 4 consecutive voxels along D
    int z = basevox % D_;
    int r = basevox / D_;
    int x = r % W_;
    r /= W_;
    int y = r % H_;
    int b = r / H_;

    // flow layout [..., 3]: 4 voxels * 3 floats = 12 floats = 3 float4 (16B aligned)
    const float4* fp = (const float4*)flow + (size_t)t * 3;
    float4 f0 = __ldg(fp + 0);
    float4 f1 = __ldg(fp + 1);
    float4 f2 = __ldg(fp + 2);
    float fl[12] = {f0.x, f0.y, f0.z, f0.w,
                    f1.x, f1.y, f1.z, f1.w,
                    f2.x, f2.y, f2.z, f2.w};

    float res[4];
#pragma unroll
    for (int i = 0; i < 4; ++i) {
        float dyv = fl[3 * i + 0];  // flow[...,0] -> dy (H axis)
        float dxv = fl[3 * i + 1];  // flow[...,1] -> dx (W axis)
        float dzv = fl[3 * i + 2];  // flow[...,2] -> dz (D axis)
        res[i] = sample1(im, b,
                         dxv + (float)x,
                         dyv + (float)y,
                         dzv + (float)(z + i));
    }

    float4 o = make_float4(res[0], res[1], res[2], res[3]);
    ((float4*)out)[t] = o;
}

extern "C" void kernel_launch(void* const* d_in, const int* in_sizes, int n_in,
                              void* d_out, int out_size) {
    const float* im = (const float*)d_in[0];    // image [4,160,160,160,1]
    const float* flow = (const float*)d_in[1];  // flow  [4,160,160,160,3]
    float* out = (float*)d_out;                 // out   [4,160,160,160,1]
    int grid = (NQUAD + 255) / 256;
    dense3d_warp_kernel<<<grid, 256>>>(im, flow, out);
}

// round 2
// speedup vs baseline: 1.0526x; 1.0526x over previous
#include <cuda_runtime.h>

namespace {
constexpr int B_ = 4, H_ = 160, W_ = 160, D_ = 160;
constexpr int SX = D_;            // stride of x (W axis)
constexpr int SY = W_ * D_;       // stride of y (H axis)
constexpr int SB = H_ * W_ * D_;  // stride of batch
constexpr int NVOX = B_ * SB;     // 16,384,000
constexpr int TPB = 320;          // exactly 2 columns of D=160 (divisible by 32)
constexpr int NBLK = NVOX / TPB;  // 51,200

__device__ __forceinline__ float sample1(const float* __restrict__ im,
                                         int b, float xf, float yf, float zf) {
    // floor + clip exactly like the reference:
    //   x0 = clip(floor(x)); x1 = clip(floor(x)+1); ddx = float(x1) - x
    int x0 = (int)floorf(xf);
    int y0 = (int)floorf(yf);
    int z0 = (int)floorf(zf);
    int x1 = min(max(x0 + 1, 0), W_ - 1);
    int y1 = min(max(y0 + 1, 0), H_ - 1);
    int z1 = min(max(z0 + 1, 0), D_ - 1);
    x0 = min(max(x0, 0), W_ - 1);
    y0 = min(max(y0, 0), H_ - 1);
    z0 = min(max(z0, 0), D_ - 1);

    float ddx = (float)x1 - xf;
    float ddy = (float)y1 - yf;
    float ddz = (float)z1 - zf;
    float ex = 1.0f - ddx;
    float ey = 1.0f - ddy;
    float ez = 1.0f - ddz;

    const float* base = im + b * SB;
    const float* p00 = base + y0 * SY + x0 * SX;  // (y0, x0)
    const float* p10 = base + y1 * SY + x0 * SX;  // (y1, x0)
    const float* p01 = base + y0 * SY + x1 * SX;  // (y0, x1)
    const float* p11 = base + y1 * SY + x1 * SX;  // (y1, x1)

    float va = __ldg(p00 + z0);
    float vb = __ldg(p10 + z0);
    float vc = __ldg(p01 + z0);
    float vd = __ldg(p11 + z0);
    float ve = __ldg(p00 + z1);
    float vf = __ldg(p10 + z1);
    float vg = __ldg(p01 + z1);
    float vh = __ldg(p11 + z1);

    float s0 = fmaf(ddx, fmaf(ddy, va, ey * vb), ex * fmaf(ddy, vc, ey * vd));
    float s1 = fmaf(ddx, fmaf(ddy, ve, ey * vf), ex * fmaf(ddy, vg, ey * vh));
    return fmaf(ddz, s0, ez * s1);
}
}  // namespace

__global__ void __launch_bounds__(TPB)
dense3d_warp_kernel(const float* __restrict__ im,
                    const float* __restrict__ flow,
                    float* __restrict__ out) {
    int tid = threadIdx.x;
    // One thread = one voxel. Lane-consecutive = z-consecutive.
    // Block covers exactly 2 (b,y,x) columns of 160 z-voxels each.
    int half = (tid >= D_) ? 1 : 0;
    int z = tid - half * D_;
    int col = blockIdx.x * 2 + half;  // global column index over B*H*W
    int x = col % W_;
    int r = col / W_;
    int y = r % H_;
    int b = r / H_;

    int v = col * D_ + z;  // global voxel index

    const float* fp = flow + (size_t)v * 3;
    float dyv = __ldg(fp + 0);  // flow[...,0] -> dy (H axis)
    float dxv = __ldg(fp + 1);  // flow[...,1] -> dx (W axis)
    float dzv = __ldg(fp + 2);  // flow[...,2] -> dz (D axis)

    out[v] = sample1(im, b,
                     dxv + (float)x,
                     dyv + (float)y,
                     dzv + (float)z);
}

extern "C" void kernel_launch(void* const* d_in, const int* in_sizes, int n_in,
                              void* d_out, int out_size) {
    const float* im = (const float*)d_in[0];    // image [4,160,160,160,1]
    const float* flow = (const float*)d_in[1];  // flow  [4,160,160,160,3]
    float* out = (float*)d_out;                 // out   [4,160,160,160,1]
    dense3d_warp_kernel<<<NBLK, TPB>>>(im, flow, out);
}